// round 9
// baseline (speedup 1.0000x reference)
#include <cuda_runtime.h>
#include <cuda_bf16.h>
#include <cuda_fp16.h>
#include <cstdint>

#define NN 50000
#define NE 800000
#define FMAX 220
#define H16S 256   // fp16 activation row stride (halves) = 512 B = 4 L2 lines

// ---------------- scratch (static device globals; no allocation) ------------
__device__ int   g_is64;
__device__ int   g_src[NE];
__device__ int   g_dst[NE];
__device__ int   g_deg_out[NN];
__device__ int   g_deg_in[NN];
__device__ float g_inv_out[NN];
__device__ float g_inv_in[NN];
__device__ int   g_rowptr[NN + 1];
__device__ int   g_cursor[NN];
__device__ int   g_col[NE];
__device__ __align__(16) float  g_bufA[(size_t)NN * FMAX];   // fp32 agg output / GEMM A
__device__ __align__(16) __half g_h16[(size_t)NN * H16S];    // fp16 activations (padded)

// ---------------- dtype detection + conversion ------------------------------
__global__ void k_detect(const int* __restrict__ ei32) {
    int lane = threadIdx.x & 31;
    int nz = (ei32[2 * lane + 1] != 0) ? 1 : 0;
    unsigned any = __ballot_sync(0xFFFFFFFFu, nz);
    if (lane == 0) g_is64 = (any == 0) ? 1 : 0;
}

__global__ void k_convert(const void* __restrict__ ei) {
    int e = blockIdx.x * blockDim.x + threadIdx.x;
    if (e >= NE) return;
    int s, d;
    if (g_is64) {
        const long long* p = (const long long*)ei;
        s = (int)p[e];
        d = (int)p[NE + e];
    } else {
        const int* p = (const int*)ei;
        s = p[e];
        d = p[NE + e];
    }
    g_src[e] = s;
    g_dst[e] = d;
}

// ---------------- graph prep ------------------------------------------------
__global__ void k_init_deg() {
    int i = blockIdx.x * blockDim.x + threadIdx.x;
    if (i < NN) { g_deg_out[i] = 0; g_deg_in[i] = 0; }
}

__global__ void k_degrees() {
    int e = blockIdx.x * blockDim.x + threadIdx.x;
    if (e < NE) {
        int s = g_src[e], d = g_dst[e];
        if ((unsigned)s < NN) atomicAdd(&g_deg_out[s], 1);
        if ((unsigned)d < NN) atomicAdd(&g_deg_in[d], 1);
    }
}

__global__ void k_invsqrt() {
    int i = blockIdx.x * blockDim.x + threadIdx.x;
    if (i < NN) {
        g_inv_out[i] = rsqrtf(fmaxf((float)g_deg_out[i], 1.0f));
        g_inv_in[i]  = rsqrtf(fmaxf((float)g_deg_in[i],  1.0f));
    }
}

__global__ void k_scan() {
    __shared__ int partial[1024];
    const int T = 1024;
    int t = threadIdx.x;
    const int chunk = (NN + T - 1) / T;
    int lo = t * chunk;
    int hi = min(lo + chunk, NN);
    int mysum = 0;
    for (int i = lo; i < hi; i++) mysum += g_deg_in[i];
    partial[t] = mysum;
    __syncthreads();
    for (int off = 1; off < T; off <<= 1) {
        int v = (t >= off) ? partial[t - off] : 0;
        __syncthreads();
        partial[t] += v;
        __syncthreads();
    }
    int run = partial[t] - mysum;
    for (int i = lo; i < hi; i++) {
        g_rowptr[i] = run;
        g_cursor[i] = run;
        run += g_deg_in[i];
    }
    if (t == 0) g_rowptr[NN] = partial[T - 1];
}

__global__ void k_fill() {
    int e = blockIdx.x * blockDim.x + threadIdx.x;
    if (e < NE) {
        int s = g_src[e];
        int d = g_dst[e];
        if ((unsigned)d < NN && (unsigned)s < NN) {
            int pos = atomicAdd(&g_cursor[d], 1);
            g_col[pos] = s;
        }
    }
}

// ---------------- aggregation (scalar fp32, F small) ------------------------
template <int F, bool SCALE_SRC, bool ADD_BIAS>
__global__ void k_aggregate(const float* __restrict__ in, float* __restrict__ out,
                            const float* __restrict__ bias) {
    int warps_per_block = blockDim.x >> 5;
    int node = blockIdx.x * warps_per_block + (threadIdx.x >> 5);
    if (node >= NN) return;
    int lane = threadIdx.x & 31;
    constexpr int J = (F + 31) / 32;
    float acc[J];
#pragma unroll
    for (int j = 0; j < J; j++) acc[j] = 0.0f;

    int lo = g_rowptr[node];
    int hi = g_rowptr[node + 1];
    for (int e = lo; e < hi; e++) {
        int s = g_col[e];
        float sc = SCALE_SRC ? g_inv_out[s] : 1.0f;
        const float* row = in + (size_t)s * F;
#pragma unroll
        for (int j = 0; j < J; j++) {
            int f = lane + 32 * j;
            if (f < F) acc[j] += row[f] * sc;
        }
    }
    float oi = g_inv_in[node];
    float* orow = out + (size_t)node * F;
#pragma unroll
    for (int j = 0; j < J; j++) {
        int f = lane + 32 * j;
        if (f < F) {
            float v = acc[j] * oi;
            if (ADD_BIAS) v += bias[f];
            orow[f] = v;
        }
    }
}

// ---------------- aggregation F=220 from fp16 padded rows -------------------
// in: __half rows, stride H16S (=256 halves, 512B). lane<28 each loads one
// uint4 (8 halves); accumulates fp32; writes fp32 rows stride 220.
__global__ void k_aggregate220_f16(const __half* __restrict__ in,
                                   float* __restrict__ out) {
    int warps_per_block = blockDim.x >> 5;
    int node = blockIdx.x * warps_per_block + (threadIdx.x >> 5);
    if (node >= NN) return;
    int lane = threadIdx.x & 31;
    bool active = lane < 28;

    float acc[8];
#pragma unroll
    for (int j = 0; j < 8; j++) acc[j] = 0.0f;

    int lo = g_rowptr[node];
    int hi = g_rowptr[node + 1];
#pragma unroll 2
    for (int e = lo; e < hi; e++) {
        int s = g_col[e];
        float sc = g_inv_out[s];
        if (active) {
            const uint4* p = (const uint4*)(in + (size_t)s * H16S + lane * 8);
            uint4 v = *p;
            float2 f0 = __half22float2(*(const __half2*)&v.x);
            float2 f1 = __half22float2(*(const __half2*)&v.y);
            float2 f2 = __half22float2(*(const __half2*)&v.z);
            float2 f3 = __half22float2(*(const __half2*)&v.w);
            acc[0] += f0.x * sc; acc[1] += f0.y * sc;
            acc[2] += f1.x * sc; acc[3] += f1.y * sc;
            acc[4] += f2.x * sc; acc[5] += f2.y * sc;
            acc[6] += f3.x * sc; acc[7] += f3.y * sc;
        }
    }
    float oi = g_inv_in[node];
    float* orow = out + (size_t)node * 220;
    if (lane < 27) {
        float4 a = make_float4(acc[0] * oi, acc[1] * oi, acc[2] * oi, acc[3] * oi);
        float4 b = make_float4(acc[4] * oi, acc[5] * oi, acc[6] * oi, acc[7] * oi);
        *(float4*)(orow + lane * 8) = a;
        *(float4*)(orow + lane * 8 + 4) = b;
    } else if (lane == 27) {
        // halves 216..219 valid (220..223 are zero padding)
        float4 a = make_float4(acc[0] * oi, acc[1] * oi, acc[2] * oi, acc[3] * oi);
        *(float4*)(orow + 216) = a;
    }
}

// ---------------- tensor-core GEMM: split-bf16 (3 MMA) ----------------------
__device__ __forceinline__ void ldm_x4(uint32_t addr, uint32_t& r0, uint32_t& r1,
                                       uint32_t& r2, uint32_t& r3) {
    asm volatile("ldmatrix.sync.aligned.m8n8.x4.shared.b16 {%0,%1,%2,%3}, [%4];"
                 : "=r"(r0), "=r"(r1), "=r"(r2), "=r"(r3) : "r"(addr));
}

__device__ __forceinline__ void mma_bf16(float* c, const uint32_t* a, const uint32_t* b) {
    asm volatile(
        "mma.sync.aligned.m16n8k16.row.col.f32.bf16.bf16.f32 "
        "{%0,%1,%2,%3}, {%4,%5,%6,%7}, {%8,%9}, {%0,%1,%2,%3};"
        : "+f"(c[0]), "+f"(c[1]), "+f"(c[2]), "+f"(c[3])
        : "r"(a[0]), "r"(a[1]), "r"(a[2]), "r"(a[3]), "r"(b[0]), "r"(b[1]));
}

// C output: fp16 rows stride H16S, tanh applied. A fp32 stride K.
__global__ void k_gemm_mma_h(const float* __restrict__ A, const float* __restrict__ W,
                             const float* __restrict__ bias, __half* __restrict__ C,
                             int M, int K, int N) {
    constexpr int BM = 128, BN = 128, BK = 32, LDS = BK + 8;
    __shared__ __nv_bfloat16 sAh[BM * LDS], sAl[BM * LDS];
    __shared__ __nv_bfloat16 sBh[BN * LDS], sBl[BN * LDS];

    int tid = threadIdx.x;
    int wid = tid >> 5, lane = tid & 31;
    int wm = wid >> 2, wn = wid & 3;  // 2 x 4 warps; warp tile 64x32
    int bm = blockIdx.y * BM, bn = blockIdx.x * BN;
    const bool kvec = (K % 4) == 0;

    float acc[4][4][4];
#pragma unroll
    for (int i = 0; i < 4; i++)
#pragma unroll
        for (int j = 0; j < 4; j++)
#pragma unroll
            for (int t = 0; t < 4; t++) acc[i][j][t] = 0.0f;

    uint32_t sAh_b = (uint32_t)__cvta_generic_to_shared(sAh);
    uint32_t sAl_b = (uint32_t)__cvta_generic_to_shared(sAl);
    uint32_t sBh_b = (uint32_t)__cvta_generic_to_shared(sBh);
    uint32_t sBl_b = (uint32_t)__cvta_generic_to_shared(sBl);

    for (int k0 = 0; k0 < K; k0 += BK) {
        // ---- A tile: BM x BK fp32 -> bf16 hi/lo ----
#pragma unroll
        for (int i = 0; i < 4; i++) {
            int idx = tid + i * 256;
            int row = idx >> 3;
            int c4  = idx & 7;
            int gm = bm + row;
            int kb = k0 + c4 * 4;
            float v[4] = {0.f, 0.f, 0.f, 0.f};
            if (gm < M) {
                if (kvec && kb + 3 < K) {
                    float4 f = *(const float4*)(A + (size_t)gm * K + kb);
                    v[0] = f.x; v[1] = f.y; v[2] = f.z; v[3] = f.w;
                } else {
#pragma unroll
                    for (int j = 0; j < 4; j++)
                        if (kb + j < K) v[j] = A[(size_t)gm * K + kb + j];
                }
            }
#pragma unroll
            for (int j = 0; j < 4; j++) {
                __nv_bfloat16 h = __float2bfloat16(v[j]);
                __nv_bfloat16 l = __float2bfloat16(v[j] - __bfloat162float(h));
                sAh[row * LDS + c4 * 4 + j] = h;
                sAl[row * LDS + c4 * 4 + j] = l;
            }
        }
        // ---- B tile: W[k0..k0+31][bn..bn+127], float4 along n ----
#pragma unroll
        for (int i = 0; i < 4; i++) {
            int idx = tid + i * 256;      // 0..1023
            int kk = idx >> 5;            // 0..31
            int n4 = (idx & 31) * 4;      // 0..124
            int gk = k0 + kk, gn = bn + n4;
            float v[4] = {0.f, 0.f, 0.f, 0.f};
            if (gk < K) {
                if (gn + 3 < N) {
                    float4 f = *(const float4*)(W + (size_t)gk * N + gn);
                    v[0] = f.x; v[1] = f.y; v[2] = f.z; v[3] = f.w;
                } else {
#pragma unroll
                    for (int j = 0; j < 4; j++)
                        if (gn + j < N) v[j] = W[(size_t)gk * N + gn + j];
                }
            }
#pragma unroll
            for (int j = 0; j < 4; j++) {
                __nv_bfloat16 h = __float2bfloat16(v[j]);
                __nv_bfloat16 l = __float2bfloat16(v[j] - __bfloat162float(h));
                sBh[(n4 + j) * LDS + kk] = h;
                sBl[(n4 + j) * LDS + kk] = l;
            }
        }
        __syncthreads();

        // ---- compute: 2 k-steps of 16 ----
#pragma unroll
        for (int ks = 0; ks < 2; ks++) {
            int koff = ks * 16;
            uint32_t ah[4][4], al[4][4];
#pragma unroll
            for (int mf = 0; mf < 4; mf++) {
                int r = wm * 64 + mf * 16 + (lane & 15);
                uint32_t off = (uint32_t)(r * LDS + koff + ((lane >> 4) << 3)) * 2;
                ldm_x4(sAh_b + off, ah[mf][0], ah[mf][1], ah[mf][2], ah[mf][3]);
                ldm_x4(sAl_b + off, al[mf][0], al[mf][1], al[mf][2], al[mf][3]);
            }
            uint32_t bh[4][2], bl[4][2];
#pragma unroll
            for (int nf2 = 0; nf2 < 2; nf2++) {
                int n = wn * 32 + nf2 * 16 + (lane & 7) + ((lane & 16) >> 1);
                int kl = koff + (((lane >> 3) & 1) << 3);
                uint32_t off = (uint32_t)(n * LDS + kl) * 2;
                uint32_t r0, r1, r2, r3;
                ldm_x4(sBh_b + off, r0, r1, r2, r3);
                bh[nf2 * 2][0] = r0; bh[nf2 * 2][1] = r1;
                bh[nf2 * 2 + 1][0] = r2; bh[nf2 * 2 + 1][1] = r3;
                ldm_x4(sBl_b + off, r0, r1, r2, r3);
                bl[nf2 * 2][0] = r0; bl[nf2 * 2][1] = r1;
                bl[nf2 * 2 + 1][0] = r2; bl[nf2 * 2 + 1][1] = r3;
            }
#pragma unroll
            for (int mf = 0; mf < 4; mf++)
#pragma unroll
                for (int nf = 0; nf < 4; nf++) {
                    mma_bf16(acc[mf][nf], ah[mf], bh[nf]);
                    mma_bf16(acc[mf][nf], ah[mf], bl[nf]);
                    mma_bf16(acc[mf][nf], al[mf], bh[nf]);
                }
        }
        __syncthreads();
    }

    // ---- epilogue: tanh -> fp16 rows (stride H16S) ----
#pragma unroll
    for (int mf = 0; mf < 4; mf++) {
        int r0 = bm + wm * 64 + mf * 16 + (lane >> 2);
        int r1 = r0 + 8;
#pragma unroll
        for (int nf = 0; nf < 4; nf++) {
            int col = bn + wn * 32 + nf * 8 + (lane & 3) * 2;
#pragma unroll
            for (int j = 0; j < 2; j++) {
                int gn = col + j;
                if (gn >= N) continue;
                float bb = bias[gn];
                if (r0 < M)
                    C[(size_t)r0 * H16S + gn] = __float2half(tanhf(acc[mf][nf][j] + bb));
                if (r1 < M)
                    C[(size_t)r1 * H16S + gn] = __float2half(tanhf(acc[mf][nf][2 + j] + bb));
            }
        }
    }
}

// ---------------- fp32 SIMT GEMM, fp16 A input (tiny layer 3) ---------------
__global__ void k_gemm_h16(const __half* __restrict__ A, const float* __restrict__ W,
                           float* __restrict__ C, int M, int K, int N, int lda) {
    constexpr int BM = 128, BN = 64, BK = 16;
    __shared__ float As[BK][BM + 1];
    __shared__ float Bs[BK][BN];

    int bm = blockIdx.y * BM;
    int bn = blockIdx.x * BN;
    int tid = threadIdx.x;
    int tr = tid >> 4;
    int tc = tid & 15;

    float acc[8][4];
#pragma unroll
    for (int i = 0; i < 8; i++)
#pragma unroll
        for (int j = 0; j < 4; j++) acc[i][j] = 0.0f;

    for (int k0 = 0; k0 < K; k0 += BK) {
#pragma unroll
        for (int i = 0; i < 8; i++) {
            int idx = tid + i * 256;
            int m = idx >> 4;
            int kk = idx & 15;
            int gm = bm + m, gk = k0 + kk;
            float v = 0.0f;
            if (gm < M && gk < K)
                v = __half2float(A[(size_t)gm * lda + gk]) * g_inv_out[gm];
            As[kk][m] = v;
        }
#pragma unroll
        for (int i = 0; i < 4; i++) {
            int idx = tid + i * 256;
            int kk = idx >> 6;
            int n = idx & 63;
            int gk = k0 + kk, gn = bn + n;
            Bs[kk][n] = (gk < K && gn < N) ? W[(size_t)gk * N + gn] : 0.0f;
        }
        __syncthreads();
#pragma unroll
        for (int kk = 0; kk < BK; kk++) {
            float a[8], b[4];
#pragma unroll
            for (int i = 0; i < 8; i++) a[i] = As[kk][tr * 8 + i];
#pragma unroll
            for (int j = 0; j < 4; j++) b[j] = Bs[kk][tc * 4 + j];
#pragma unroll
            for (int i = 0; i < 8; i++)
#pragma unroll
                for (int j = 0; j < 4; j++) acc[i][j] += a[i] * b[j];
        }
        __syncthreads();
    }

#pragma unroll
    for (int i = 0; i < 8; i++) {
        int gm = bm + tr * 8 + i;
        if (gm >= M) continue;
#pragma unroll
        for (int j = 0; j < 4; j++) {
            int gn = bn + tc * 4 + j;
            if (gn >= N) continue;
            C[(size_t)gm * N + gn] = acc[i][j];
        }
    }
}

// ---------------- launch -----------------------------------------------------
extern "C" void kernel_launch(void* const* d_in, const int* in_sizes, int n_in,
                              void* d_out, int out_size) {
    const float* x  = nullptr;
    const float* W0 = nullptr; const float* W1 = nullptr;
    const float* W2 = nullptr; const float* W3 = nullptr;
    const float* b0 = nullptr; const float* b1 = nullptr;
    const float* b2 = nullptr; const float* b3 = nullptr;
    const void*  ei = nullptr;

    int n220 = 0, nbias = 0;
    for (int i = 0; i < n_in; i++) {
        int s = in_sizes[i];
        const void* p = d_in[i];
        switch (s) {
            case 1100000: x  = (const float*)p; break;
            case 4840:    W0 = (const float*)p; break;
            case 48400:   if (n220 == 0) W1 = (const float*)p;
                          else           W2 = (const float*)p;
                          n220++; break;
            case 2200:    W3 = (const float*)p; break;
            case 220:     if (nbias == 0) b0 = (const float*)p;
                          else if (nbias == 1) b1 = (const float*)p;
                          else b2 = (const float*)p;
                          nbias++; break;
            case 10:      b3 = (const float*)p; break;
            case 1600000: ei = p; break;
            default: break;
        }
    }
    float* out = (float*)d_out;

    float* bufA = nullptr; __half* h16 = nullptr;
    if (cudaGetSymbolAddress((void**)&bufA, g_bufA) != cudaSuccess) return;
    if (cudaGetSymbolAddress((void**)&h16, g_h16) != cudaSuccess) return;
    if (!x || !W0 || !W1 || !W2 || !W3 || !b0 || !b1 || !b2 || !b3 || !ei) return;

    const int TB = 256;
    // graph prep
    k_detect<<<1, 32>>>((const int*)ei);
    k_convert<<<(NE + TB - 1) / TB, TB>>>(ei);
    k_init_deg<<<(NN + TB - 1) / TB, TB>>>();
    k_degrees<<<(NE + TB - 1) / TB, TB>>>();
    k_invsqrt<<<(NN + TB - 1) / TB, TB>>>();
    k_scan<<<1, 1024>>>();
    k_fill<<<(NE + TB - 1) / TB, TB>>>();

    const int AGG_BLOCKS = (NN + 7) / 8;  // 8 warps/block
    dim3 mma_grid((220 + 127) / 128, (NN + 127) / 128);
    dim3 gemm_grid3(1, (NN + 127) / 128);

    // Layer 0: agg(x fp32, F=22) -> bufA ; mma 22->220 +b0, tanh -> h16
    k_aggregate<22, true, false><<<AGG_BLOCKS, TB>>>(x, bufA, nullptr);
    k_gemm_mma_h<<<mma_grid, TB>>>(bufA, W0, b0, h16, NN, 22, 220);

    // Layer 1: agg fp16 -> bufA fp32 ; mma -> h16
    k_aggregate220_f16<<<AGG_BLOCKS, TB>>>(h16, bufA);
    k_gemm_mma_h<<<mma_grid, TB>>>(bufA, W1, b1, h16, NN, 220, 220);

    // Layer 2
    k_aggregate220_f16<<<AGG_BLOCKS, TB>>>(h16, bufA);
    k_gemm_mma_h<<<mma_grid, TB>>>(bufA, W2, b2, h16, NN, 220, 220);

    // Layer 3 (reordered): z = (h*inv_out) @ W3 -> bufA[N,10]; agg 10-wide + b3
    k_gemm_h16<<<gemm_grid3, TB>>>(h16, W3, bufA, NN, 220, 10, H16S);
    k_aggregate<10, false, true><<<AGG_BLOCKS, TB>>>(bufA, out, b3);
}

// round 11
// speedup vs baseline: 1.0008x; 1.0008x over previous
#include <cuda_runtime.h>
#include <cuda_bf16.h>
#include <cuda_fp16.h>
#include <cstdint>

#define NN 50000
#define NE 800000
#define FMAX 220
#define H16S 224   // fp16 activation row stride (halves) = 448 B
// 448B stride: bit 8 of s*448 varies -> full LTS partition spread (512B stride
// kept bit 8 constant = half of L2 partitions idle -> R9 regression).
// 440B row at offset {0,64} mod 128 always spans exactly 4 lines = 512B/edge.

// ---------------- scratch (static device globals; no allocation) ------------
__device__ int   g_is64;
__device__ int   g_src[NE];
__device__ int   g_dst[NE];
__device__ int   g_deg_out[NN];
__device__ int   g_deg_in[NN];
__device__ float g_inv_out[NN];
__device__ float g_inv_in[NN];
__device__ int   g_rowptr[NN + 1];
__device__ int   g_cursor[NN];
__device__ int   g_col[NE];
__device__ __align__(16) float  g_bufA[(size_t)NN * FMAX];   // fp32 agg output / GEMM A
__device__ __align__(16) __half g_h16[(size_t)NN * H16S];    // fp16 activations (padded, zero-init)

// ---------------- dtype detection + conversion ------------------------------
__global__ void k_detect(const int* __restrict__ ei32) {
    int lane = threadIdx.x & 31;
    int nz = (ei32[2 * lane + 1] != 0) ? 1 : 0;
    unsigned any = __ballot_sync(0xFFFFFFFFu, nz);
    if (lane == 0) g_is64 = (any == 0) ? 1 : 0;
}

__global__ void k_convert(const void* __restrict__ ei) {
    int e = blockIdx.x * blockDim.x + threadIdx.x;
    if (e >= NE) return;
    int s, d;
    if (g_is64) {
        const long long* p = (const long long*)ei;
        s = (int)p[e];
        d = (int)p[NE + e];
    } else {
        const int* p = (const int*)ei;
        s = p[e];
        d = p[NE + e];
    }
    g_src[e] = s;
    g_dst[e] = d;
}

// ---------------- graph prep ------------------------------------------------
__global__ void k_init_deg() {
    int i = blockIdx.x * blockDim.x + threadIdx.x;
    if (i < NN) { g_deg_out[i] = 0; g_deg_in[i] = 0; }
}

__global__ void k_degrees() {
    int e = blockIdx.x * blockDim.x + threadIdx.x;
    if (e < NE) {
        int s = g_src[e], d = g_dst[e];
        if ((unsigned)s < NN) atomicAdd(&g_deg_out[s], 1);
        if ((unsigned)d < NN) atomicAdd(&g_deg_in[d], 1);
    }
}

__global__ void k_invsqrt() {
    int i = blockIdx.x * blockDim.x + threadIdx.x;
    if (i < NN) {
        g_inv_out[i] = rsqrtf(fmaxf((float)g_deg_out[i], 1.0f));
        g_inv_in[i]  = rsqrtf(fmaxf((float)g_deg_in[i],  1.0f));
    }
}

__global__ void k_scan() {
    __shared__ int partial[1024];
    const int T = 1024;
    int t = threadIdx.x;
    const int chunk = (NN + T - 1) / T;
    int lo = t * chunk;
    int hi = min(lo + chunk, NN);
    int mysum = 0;
    for (int i = lo; i < hi; i++) mysum += g_deg_in[i];
    partial[t] = mysum;
    __syncthreads();
    for (int off = 1; off < T; off <<= 1) {
        int v = (t >= off) ? partial[t - off] : 0;
        __syncthreads();
        partial[t] += v;
        __syncthreads();
    }
    int run = partial[t] - mysum;
    for (int i = lo; i < hi; i++) {
        g_rowptr[i] = run;
        g_cursor[i] = run;
        run += g_deg_in[i];
    }
    if (t == 0) g_rowptr[NN] = partial[T - 1];
}

__global__ void k_fill() {
    int e = blockIdx.x * blockDim.x + threadIdx.x;
    if (e < NE) {
        int s = g_src[e];
        int d = g_dst[e];
        if ((unsigned)d < NN && (unsigned)s < NN) {
            int pos = atomicAdd(&g_cursor[d], 1);
            g_col[pos] = s;
        }
    }
}

// ---------------- aggregation (scalar fp32, F small) ------------------------
template <int F, bool SCALE_SRC, bool ADD_BIAS>
__global__ void k_aggregate(const float* __restrict__ in, float* __restrict__ out,
                            const float* __restrict__ bias) {
    int warps_per_block = blockDim.x >> 5;
    int node = blockIdx.x * warps_per_block + (threadIdx.x >> 5);
    if (node >= NN) return;
    int lane = threadIdx.x & 31;
    constexpr int J = (F + 31) / 32;
    float acc[J];
#pragma unroll
    for (int j = 0; j < J; j++) acc[j] = 0.0f;

    int lo = g_rowptr[node];
    int hi = g_rowptr[node + 1];
    for (int e = lo; e < hi; e++) {
        int s = g_col[e];
        float sc = SCALE_SRC ? g_inv_out[s] : 1.0f;
        const float* row = in + (size_t)s * F;
#pragma unroll
        for (int j = 0; j < J; j++) {
            int f = lane + 32 * j;
            if (f < F) acc[j] += row[f] * sc;
        }
    }
    float oi = g_inv_in[node];
    float* orow = out + (size_t)node * F;
#pragma unroll
    for (int j = 0; j < J; j++) {
        int f = lane + 32 * j;
        if (f < F) {
            float v = acc[j] * oi;
            if (ADD_BIAS) v += bias[f];
            orow[f] = v;
        }
    }
}

// ---------------- aggregation F=220 from fp16 padded rows -------------------
// in: __half rows, stride H16S (=224 halves, 448B). lane<28 each loads one
// uint4 (8 halves; lane 27 covers 4 zero pad halves); fp32 accumulate;
// writes fp32 rows stride 220.
__global__ void k_aggregate220_f16(const __half* __restrict__ in,
                                   float* __restrict__ out) {
    int warps_per_block = blockDim.x >> 5;
    int node = blockIdx.x * warps_per_block + (threadIdx.x >> 5);
    if (node >= NN) return;
    int lane = threadIdx.x & 31;
    bool active = lane < 28;

    float acc[8];
#pragma unroll
    for (int j = 0; j < 8; j++) acc[j] = 0.0f;

    int lo = g_rowptr[node];
    int hi = g_rowptr[node + 1];
#pragma unroll 2
    for (int e = lo; e < hi; e++) {
        int s = g_col[e];
        float sc = g_inv_out[s];
        if (active) {
            const uint4* p = (const uint4*)(in + (size_t)s * H16S + lane * 8);
            uint4 v = *p;
            float2 f0 = __half22float2(*(const __half2*)&v.x);
            float2 f1 = __half22float2(*(const __half2*)&v.y);
            float2 f2 = __half22float2(*(const __half2*)&v.z);
            float2 f3 = __half22float2(*(const __half2*)&v.w);
            acc[0] += f0.x * sc; acc[1] += f0.y * sc;
            acc[2] += f1.x * sc; acc[3] += f1.y * sc;
            acc[4] += f2.x * sc; acc[5] += f2.y * sc;
            acc[6] += f3.x * sc; acc[7] += f3.y * sc;
        }
    }
    float oi = g_inv_in[node];
    float* orow = out + (size_t)node * 220;
    if (lane < 27) {
        float4 a = make_float4(acc[0] * oi, acc[1] * oi, acc[2] * oi, acc[3] * oi);
        float4 b = make_float4(acc[4] * oi, acc[5] * oi, acc[6] * oi, acc[7] * oi);
        *(float4*)(orow + lane * 8) = a;
        *(float4*)(orow + lane * 8 + 4) = b;
    } else if (lane == 27) {
        // halves 216..219 valid (220..223 are zero padding)
        float4 a = make_float4(acc[0] * oi, acc[1] * oi, acc[2] * oi, acc[3] * oi);
        *(float4*)(orow + 216) = a;
    }
}

// ---------------- tensor-core GEMM: split-bf16 (3 MMA) ----------------------
__device__ __forceinline__ void ldm_x4(uint32_t addr, uint32_t& r0, uint32_t& r1,
                                       uint32_t& r2, uint32_t& r3) {
    asm volatile("ldmatrix.sync.aligned.m8n8.x4.shared.b16 {%0,%1,%2,%3}, [%4];"
                 : "=r"(r0), "=r"(r1), "=r"(r2), "=r"(r3) : "r"(addr));
}

__device__ __forceinline__ void mma_bf16(float* c, const uint32_t* a, const uint32_t* b) {
    asm volatile(
        "mma.sync.aligned.m16n8k16.row.col.f32.bf16.bf16.f32 "
        "{%0,%1,%2,%3}, {%4,%5,%6,%7}, {%8,%9}, {%0,%1,%2,%3};"
        : "+f"(c[0]), "+f"(c[1]), "+f"(c[2]), "+f"(c[3])
        : "r"(a[0]), "r"(a[1]), "r"(a[2]), "r"(a[3]), "r"(b[0]), "r"(b[1]));
}

// C output: fp16 rows stride H16S, tanh applied. A fp32 stride K.
__global__ void k_gemm_mma_h(const float* __restrict__ A, const float* __restrict__ W,
                             const float* __restrict__ bias, __half* __restrict__ C,
                             int M, int K, int N) {
    constexpr int BM = 128, BN = 128, BK = 32, LDS = BK + 8;
    __shared__ __nv_bfloat16 sAh[BM * LDS], sAl[BM * LDS];
    __shared__ __nv_bfloat16 sBh[BN * LDS], sBl[BN * LDS];

    int tid = threadIdx.x;
    int wid = tid >> 5, lane = tid & 31;
    int wm = wid >> 2, wn = wid & 3;  // 2 x 4 warps; warp tile 64x32
    int bm = blockIdx.y * BM, bn = blockIdx.x * BN;
    const bool kvec = (K % 4) == 0;

    float acc[4][4][4];
#pragma unroll
    for (int i = 0; i < 4; i++)
#pragma unroll
        for (int j = 0; j < 4; j++)
#pragma unroll
            for (int t = 0; t < 4; t++) acc[i][j][t] = 0.0f;

    uint32_t sAh_b = (uint32_t)__cvta_generic_to_shared(sAh);
    uint32_t sAl_b = (uint32_t)__cvta_generic_to_shared(sAl);
    uint32_t sBh_b = (uint32_t)__cvta_generic_to_shared(sBh);
    uint32_t sBl_b = (uint32_t)__cvta_generic_to_shared(sBl);

    for (int k0 = 0; k0 < K; k0 += BK) {
        // ---- A tile: BM x BK fp32 -> bf16 hi/lo ----
#pragma unroll
        for (int i = 0; i < 4; i++) {
            int idx = tid + i * 256;
            int row = idx >> 3;
            int c4  = idx & 7;
            int gm = bm + row;
            int kb = k0 + c4 * 4;
            float v[4] = {0.f, 0.f, 0.f, 0.f};
            if (gm < M) {
                if (kvec && kb + 3 < K) {
                    float4 f = *(const float4*)(A + (size_t)gm * K + kb);
                    v[0] = f.x; v[1] = f.y; v[2] = f.z; v[3] = f.w;
                } else {
#pragma unroll
                    for (int j = 0; j < 4; j++)
                        if (kb + j < K) v[j] = A[(size_t)gm * K + kb + j];
                }
            }
#pragma unroll
            for (int j = 0; j < 4; j++) {
                __nv_bfloat16 h = __float2bfloat16(v[j]);
                __nv_bfloat16 l = __float2bfloat16(v[j] - __bfloat162float(h));
                sAh[row * LDS + c4 * 4 + j] = h;
                sAl[row * LDS + c4 * 4 + j] = l;
            }
        }
        // ---- B tile: W[k0..k0+31][bn..bn+127], float4 along n ----
#pragma unroll
        for (int i = 0; i < 4; i++) {
            int idx = tid + i * 256;      // 0..1023
            int kk = idx >> 5;            // 0..31
            int n4 = (idx & 31) * 4;      // 0..124
            int gk = k0 + kk, gn = bn + n4;
            float v[4] = {0.f, 0.f, 0.f, 0.f};
            if (gk < K) {
                if (gn + 3 < N) {
                    float4 f = *(const float4*)(W + (size_t)gk * N + gn);
                    v[0] = f.x; v[1] = f.y; v[2] = f.z; v[3] = f.w;
                } else {
#pragma unroll
                    for (int j = 0; j < 4; j++)
                        if (gn + j < N) v[j] = W[(size_t)gk * N + gn + j];
                }
            }
#pragma unroll
            for (int j = 0; j < 4; j++) {
                __nv_bfloat16 h = __float2bfloat16(v[j]);
                __nv_bfloat16 l = __float2bfloat16(v[j] - __bfloat162float(h));
                sBh[(n4 + j) * LDS + kk] = h;
                sBl[(n4 + j) * LDS + kk] = l;
            }
        }
        __syncthreads();

        // ---- compute: 2 k-steps of 16 ----
#pragma unroll
        for (int ks = 0; ks < 2; ks++) {
            int koff = ks * 16;
            uint32_t ah[4][4], al[4][4];
#pragma unroll
            for (int mf = 0; mf < 4; mf++) {
                int r = wm * 64 + mf * 16 + (lane & 15);
                uint32_t off = (uint32_t)(r * LDS + koff + ((lane >> 4) << 3)) * 2;
                ldm_x4(sAh_b + off, ah[mf][0], ah[mf][1], ah[mf][2], ah[mf][3]);
                ldm_x4(sAl_b + off, al[mf][0], al[mf][1], al[mf][2], al[mf][3]);
            }
            uint32_t bh[4][2], bl[4][2];
#pragma unroll
            for (int nf2 = 0; nf2 < 2; nf2++) {
                int n = wn * 32 + nf2 * 16 + (lane & 7) + ((lane & 16) >> 1);
                int kl = koff + (((lane >> 3) & 1) << 3);
                uint32_t off = (uint32_t)(n * LDS + kl) * 2;
                uint32_t r0, r1, r2, r3;
                ldm_x4(sBh_b + off, r0, r1, r2, r3);
                bh[nf2 * 2][0] = r0; bh[nf2 * 2][1] = r1;
                bh[nf2 * 2 + 1][0] = r2; bh[nf2 * 2 + 1][1] = r3;
                ldm_x4(sBl_b + off, r0, r1, r2, r3);
                bl[nf2 * 2][0] = r0; bl[nf2 * 2][1] = r1;
                bl[nf2 * 2 + 1][0] = r2; bl[nf2 * 2 + 1][1] = r3;
            }
#pragma unroll
            for (int mf = 0; mf < 4; mf++)
#pragma unroll
                for (int nf = 0; nf < 4; nf++) {
                    mma_bf16(acc[mf][nf], ah[mf], bh[nf]);
                    mma_bf16(acc[mf][nf], ah[mf], bl[nf]);
                    mma_bf16(acc[mf][nf], al[mf], bh[nf]);
                }
        }
        __syncthreads();
    }

    // ---- epilogue: tanh -> fp16 rows (stride H16S) ----
#pragma unroll
    for (int mf = 0; mf < 4; mf++) {
        int r0 = bm + wm * 64 + mf * 16 + (lane >> 2);
        int r1 = r0 + 8;
#pragma unroll
        for (int nf = 0; nf < 4; nf++) {
            int col = bn + wn * 32 + nf * 8 + (lane & 3) * 2;
#pragma unroll
            for (int j = 0; j < 2; j++) {
                int gn = col + j;
                if (gn >= N) continue;
                float bb = bias[gn];
                if (r0 < M)
                    C[(size_t)r0 * H16S + gn] = __float2half(tanhf(acc[mf][nf][j] + bb));
                if (r1 < M)
                    C[(size_t)r1 * H16S + gn] = __float2half(tanhf(acc[mf][nf][2 + j] + bb));
            }
        }
    }
}

// ---------------- fp32 SIMT GEMM, fp16 A input (tiny layer 3) ---------------
__global__ void k_gemm_h16(const __half* __restrict__ A, const float* __restrict__ W,
                           float* __restrict__ C, int M, int K, int N, int lda) {
    constexpr int BM = 128, BN = 64, BK = 16;
    __shared__ float As[BK][BM + 1];
    __shared__ float Bs[BK][BN];

    int bm = blockIdx.y * BM;
    int bn = blockIdx.x * BN;
    int tid = threadIdx.x;
    int tr = tid >> 4;
    int tc = tid & 15;

    float acc[8][4];
#pragma unroll
    for (int i = 0; i < 8; i++)
#pragma unroll
        for (int j = 0; j < 4; j++) acc[i][j] = 0.0f;

    for (int k0 = 0; k0 < K; k0 += BK) {
#pragma unroll
        for (int i = 0; i < 8; i++) {
            int idx = tid + i * 256;
            int m = idx >> 4;
            int kk = idx & 15;
            int gm = bm + m, gk = k0 + kk;
            float v = 0.0f;
            if (gm < M && gk < K)
                v = __half2float(A[(size_t)gm * lda + gk]) * g_inv_out[gm];
            As[kk][m] = v;
        }
#pragma unroll
        for (int i = 0; i < 4; i++) {
            int idx = tid + i * 256;
            int kk = idx >> 6;
            int n = idx & 63;
            int gk = k0 + kk, gn = bn + n;
            Bs[kk][n] = (gk < K && gn < N) ? W[(size_t)gk * N + gn] : 0.0f;
        }
        __syncthreads();
#pragma unroll
        for (int kk = 0; kk < BK; kk++) {
            float a[8], b[4];
#pragma unroll
            for (int i = 0; i < 8; i++) a[i] = As[kk][tr * 8 + i];
#pragma unroll
            for (int j = 0; j < 4; j++) b[j] = Bs[kk][tc * 4 + j];
#pragma unroll
            for (int i = 0; i < 8; i++)
#pragma unroll
                for (int j = 0; j < 4; j++) acc[i][j] += a[i] * b[j];
        }
        __syncthreads();
    }

#pragma unroll
    for (int i = 0; i < 8; i++) {
        int gm = bm + tr * 8 + i;
        if (gm >= M) continue;
#pragma unroll
        for (int j = 0; j < 4; j++) {
            int gn = bn + tc * 4 + j;
            if (gn >= N) continue;
            C[(size_t)gm * N + gn] = acc[i][j];
        }
    }
}

// ---------------- launch -----------------------------------------------------
extern "C" void kernel_launch(void* const* d_in, const int* in_sizes, int n_in,
                              void* d_out, int out_size) {
    const float* x  = nullptr;
    const float* W0 = nullptr; const float* W1 = nullptr;
    const float* W2 = nullptr; const float* W3 = nullptr;
    const float* b0 = nullptr; const float* b1 = nullptr;
    const float* b2 = nullptr; const float* b3 = nullptr;
    const void*  ei = nullptr;

    int n220 = 0, nbias = 0;
    for (int i = 0; i < n_in; i++) {
        int s = in_sizes[i];
        const void* p = d_in[i];
        switch (s) {
            case 1100000: x  = (const float*)p; break;
            case 4840:    W0 = (const float*)p; break;
            case 48400:   if (n220 == 0) W1 = (const float*)p;
                          else           W2 = (const float*)p;
                          n220++; break;
            case 2200:    W3 = (const float*)p; break;
            case 220:     if (nbias == 0) b0 = (const float*)p;
                          else if (nbias == 1) b1 = (const float*)p;
                          else b2 = (const float*)p;
                          nbias++; break;
            case 10:      b3 = (const float*)p; break;
            case 1600000: ei = p; break;
            default: break;
        }
    }
    float* out = (float*)d_out;

    float* bufA = nullptr; __half* h16 = nullptr;
    if (cudaGetSymbolAddress((void**)&bufA, g_bufA) != cudaSuccess) return;
    if (cudaGetSymbolAddress((void**)&h16, g_h16) != cudaSuccess) return;
    if (!x || !W0 || !W1 || !W2 || !W3 || !b0 || !b1 || !b2 || !b3 || !ei) return;

    const int TB = 256;
    // graph prep
    k_detect<<<1, 32>>>((const int*)ei);
    k_convert<<<(NE + TB - 1) / TB, TB>>>(ei);
    k_init_deg<<<(NN + TB - 1) / TB, TB>>>();
    k_degrees<<<(NE + TB - 1) / TB, TB>>>();
    k_invsqrt<<<(NN + TB - 1) / TB, TB>>>();
    k_scan<<<1, 1024>>>();
    k_fill<<<(NE + TB - 1) / TB, TB>>>();

    const int AGG_BLOCKS = (NN + 7) / 8;  // 8 warps/block
    dim3 mma_grid((220 + 127) / 128, (NN + 127) / 128);
    dim3 gemm_grid3(1, (NN + 127) / 128);

    // Layer 0: agg(x fp32, F=22) -> bufA ; mma 22->220 +b0, tanh -> h16
    k_aggregate<22, true, false><<<AGG_BLOCKS, TB>>>(x, bufA, nullptr);
    k_gemm_mma_h<<<mma_grid, TB>>>(bufA, W0, b0, h16, NN, 22, 220);

    // Layer 1: agg fp16 -> bufA fp32 ; mma -> h16
    k_aggregate220_f16<<<AGG_BLOCKS, TB>>>(h16, bufA);
    k_gemm_mma_h<<<mma_grid, TB>>>(bufA, W1, b1, h16, NN, 220, 220);

    // Layer 2
    k_aggregate220_f16<<<AGG_BLOCKS, TB>>>(h16, bufA);
    k_gemm_mma_h<<<mma_grid, TB>>>(bufA, W2, b2, h16, NN, 220, 220);

    // Layer 3 (reordered): z = (h*inv_out) @ W3 -> bufA[N,10]; agg 10-wide + b3
    k_gemm_h16<<<gemm_grid3, TB>>>(h16, W3, bufA, NN, 220, 10, H16S);
    k_aggregate<10, false, true><<<AGG_BLOCKS, TB>>>(bufA, out, b3);
}

// round 12
// speedup vs baseline: 1.0180x; 1.0171x over previous
#include <cuda_runtime.h>
#include <cuda_bf16.h>
#include <cuda_fp16.h>
#include <cstdint>

#define NN 50000
#define NE 800000
#define FMAX 220
#define H16S 224   // fp16 activation row stride (halves) = 448 B

// ---------------- scratch (static device globals; no allocation) ------------
__device__ int   g_is64;
__device__ int   g_src[NE];
__device__ int   g_dst[NE];
__device__ int   g_deg_out[NN];
__device__ int   g_deg_in[NN];
__device__ float g_inv_out[NN];
__device__ float g_inv_in[NN];
__device__ int   g_rowptr[NN + 1];
__device__ int   g_cursor[NN];
__device__ int   g_col[NE];
__device__ __align__(16) float  g_bufA[(size_t)NN * FMAX];   // fp32 agg output / GEMM A
__device__ __align__(16) __half g_h16[(size_t)NN * H16S];    // fp16 activations (padded, zero-init)

// ---------------- dtype detection + conversion ------------------------------
__global__ void k_detect(const int* __restrict__ ei32) {
    int lane = threadIdx.x & 31;
    int nz = (ei32[2 * lane + 1] != 0) ? 1 : 0;
    unsigned any = __ballot_sync(0xFFFFFFFFu, nz);
    if (lane == 0) g_is64 = (any == 0) ? 1 : 0;
}

__global__ void k_convert(const void* __restrict__ ei) {
    int e = blockIdx.x * blockDim.x + threadIdx.x;
    if (e >= NE) return;
    int s, d;
    if (g_is64) {
        const long long* p = (const long long*)ei;
        s = (int)p[e];
        d = (int)p[NE + e];
    } else {
        const int* p = (const int*)ei;
        s = p[e];
        d = p[NE + e];
    }
    g_src[e] = s;
    g_dst[e] = d;
}

// ---------------- graph prep ------------------------------------------------
__global__ void k_init_deg() {
    int i = blockIdx.x * blockDim.x + threadIdx.x;
    if (i < NN) { g_deg_out[i] = 0; g_deg_in[i] = 0; }
}

__global__ void k_degrees() {
    int e = blockIdx.x * blockDim.x + threadIdx.x;
    if (e < NE) {
        int s = g_src[e], d = g_dst[e];
        if ((unsigned)s < NN) atomicAdd(&g_deg_out[s], 1);
        if ((unsigned)d < NN) atomicAdd(&g_deg_in[d], 1);
    }
}

__global__ void k_invsqrt() {
    int i = blockIdx.x * blockDim.x + threadIdx.x;
    if (i < NN) {
        g_inv_out[i] = rsqrtf(fmaxf((float)g_deg_out[i], 1.0f));
        g_inv_in[i]  = rsqrtf(fmaxf((float)g_deg_in[i],  1.0f));
    }
}

__global__ void k_scan() {
    __shared__ int partial[1024];
    const int T = 1024;
    int t = threadIdx.x;
    const int chunk = (NN + T - 1) / T;
    int lo = t * chunk;
    int hi = min(lo + chunk, NN);
    int mysum = 0;
    for (int i = lo; i < hi; i++) mysum += g_deg_in[i];
    partial[t] = mysum;
    __syncthreads();
    for (int off = 1; off < T; off <<= 1) {
        int v = (t >= off) ? partial[t - off] : 0;
        __syncthreads();
        partial[t] += v;
        __syncthreads();
    }
    int run = partial[t] - mysum;
    for (int i = lo; i < hi; i++) {
        g_rowptr[i] = run;
        g_cursor[i] = run;
        run += g_deg_in[i];
    }
    if (t == 0) g_rowptr[NN] = partial[T - 1];
}

__global__ void k_fill() {
    int e = blockIdx.x * blockDim.x + threadIdx.x;
    if (e < NE) {
        int s = g_src[e];
        int d = g_dst[e];
        if ((unsigned)d < NN && (unsigned)s < NN) {
            int pos = atomicAdd(&g_cursor[d], 1);
            g_col[pos] = s;
        }
    }
}

// ---------------- aggregation (scalar fp32, F small), 4-edge batched --------
template <int F, bool SCALE_SRC, bool ADD_BIAS>
__global__ void k_aggregate(const float* __restrict__ in, float* __restrict__ out,
                            const float* __restrict__ bias) {
    int warps_per_block = blockDim.x >> 5;
    int node = blockIdx.x * warps_per_block + (threadIdx.x >> 5);
    if (node >= NN) return;
    int lane = threadIdx.x & 31;
    constexpr int J = (F + 31) / 32;
    float acc[J];
#pragma unroll
    for (int j = 0; j < J; j++) acc[j] = 0.0f;

    int lo = g_rowptr[node];
    int hi = g_rowptr[node + 1];
    int e = lo;
    for (; e + 3 < hi; e += 4) {
        int s0 = g_col[e], s1 = g_col[e + 1], s2 = g_col[e + 2], s3 = g_col[e + 3];
        float c0 = SCALE_SRC ? g_inv_out[s0] : 1.0f;
        float c1 = SCALE_SRC ? g_inv_out[s1] : 1.0f;
        float c2 = SCALE_SRC ? g_inv_out[s2] : 1.0f;
        float c3 = SCALE_SRC ? g_inv_out[s3] : 1.0f;
#pragma unroll
        for (int j = 0; j < J; j++) {
            int f = lane + 32 * j;
            if (f < F) {
                float v0 = in[(size_t)s0 * F + f];
                float v1 = in[(size_t)s1 * F + f];
                float v2 = in[(size_t)s2 * F + f];
                float v3 = in[(size_t)s3 * F + f];
                acc[j] += v0 * c0 + v1 * c1 + v2 * c2 + v3 * c3;
            }
        }
    }
    for (; e < hi; e++) {
        int s = g_col[e];
        float sc = SCALE_SRC ? g_inv_out[s] : 1.0f;
#pragma unroll
        for (int j = 0; j < J; j++) {
            int f = lane + 32 * j;
            if (f < F) acc[j] += in[(size_t)s * F + f] * sc;
        }
    }
    float oi = g_inv_in[node];
    float* orow = out + (size_t)node * F;
#pragma unroll
    for (int j = 0; j < J; j++) {
        int f = lane + 32 * j;
        if (f < F) {
            float v = acc[j] * oi;
            if (ADD_BIAS) v += bias[f];
            orow[f] = v;
        }
    }
}

// ---------------- aggregation F=220 fp16 rows, 8-edge batched ---------------
__device__ __forceinline__ void acc_h8(float* acc, uint4 v, float sc) {
    float2 f0 = __half22float2(*(const __half2*)&v.x);
    float2 f1 = __half22float2(*(const __half2*)&v.y);
    float2 f2 = __half22float2(*(const __half2*)&v.z);
    float2 f3 = __half22float2(*(const __half2*)&v.w);
    acc[0] += f0.x * sc; acc[1] += f0.y * sc;
    acc[2] += f1.x * sc; acc[3] += f1.y * sc;
    acc[4] += f2.x * sc; acc[5] += f2.y * sc;
    acc[6] += f3.x * sc; acc[7] += f3.y * sc;
}

__global__ void k_aggregate220_f16(const __half* __restrict__ in,
                                   float* __restrict__ out) {
    int warps_per_block = blockDim.x >> 5;
    int node = blockIdx.x * warps_per_block + (threadIdx.x >> 5);
    if (node >= NN) return;
    int lane = threadIdx.x & 31;
    bool active = lane < 28;
    unsigned loff = lane * 8u;  // halves

    float acc[8];
#pragma unroll
    for (int j = 0; j < 8; j++) acc[j] = 0.0f;

    int lo = g_rowptr[node];
    int hi = g_rowptr[node + 1];
    int e = lo;
    // 8-edge batches: 8 independent LDG.128s in flight per lane (MLP ~8)
    for (; e + 7 < hi; e += 8) {
        int s[8];
#pragma unroll
        for (int q = 0; q < 8; q++) s[q] = g_col[e + q];
        float c[8];
#pragma unroll
        for (int q = 0; q < 8; q++) c[q] = g_inv_out[s[q]];
        if (active) {
            uint4 v[8];
#pragma unroll
            for (int q = 0; q < 8; q++)
                v[q] = *(const uint4*)(in + (size_t)s[q] * H16S + loff);
#pragma unroll
            for (int q = 0; q < 8; q++) acc_h8(acc, v[q], c[q]);
        }
    }
    // 2-edge tail batches
    for (; e + 1 < hi; e += 2) {
        int s0 = g_col[e], s1 = g_col[e + 1];
        float c0 = g_inv_out[s0], c1 = g_inv_out[s1];
        if (active) {
            uint4 v0 = *(const uint4*)(in + (size_t)s0 * H16S + loff);
            uint4 v1 = *(const uint4*)(in + (size_t)s1 * H16S + loff);
            acc_h8(acc, v0, c0);
            acc_h8(acc, v1, c1);
        }
    }
    for (; e < hi; e++) {
        int s0 = g_col[e];
        float c0 = g_inv_out[s0];
        if (active) {
            uint4 v0 = *(const uint4*)(in + (size_t)s0 * H16S + loff);
            acc_h8(acc, v0, c0);
        }
    }

    float oi = g_inv_in[node];
    float* orow = out + (size_t)node * 220;
    if (lane < 27) {
        float4 a = make_float4(acc[0] * oi, acc[1] * oi, acc[2] * oi, acc[3] * oi);
        float4 b = make_float4(acc[4] * oi, acc[5] * oi, acc[6] * oi, acc[7] * oi);
        *(float4*)(orow + lane * 8) = a;
        *(float4*)(orow + lane * 8 + 4) = b;
    } else if (lane == 27) {
        float4 a = make_float4(acc[0] * oi, acc[1] * oi, acc[2] * oi, acc[3] * oi);
        *(float4*)(orow + 216) = a;
    }
}

// ---------------- tensor-core GEMM: split-bf16 (3 MMA) ----------------------
__device__ __forceinline__ void ldm_x4(uint32_t addr, uint32_t& r0, uint32_t& r1,
                                       uint32_t& r2, uint32_t& r3) {
    asm volatile("ldmatrix.sync.aligned.m8n8.x4.shared.b16 {%0,%1,%2,%3}, [%4];"
                 : "=r"(r0), "=r"(r1), "=r"(r2), "=r"(r3) : "r"(addr));
}

__device__ __forceinline__ void mma_bf16(float* c, const uint32_t* a, const uint32_t* b) {
    asm volatile(
        "mma.sync.aligned.m16n8k16.row.col.f32.bf16.bf16.f32 "
        "{%0,%1,%2,%3}, {%4,%5,%6,%7}, {%8,%9}, {%0,%1,%2,%3};"
        : "+f"(c[0]), "+f"(c[1]), "+f"(c[2]), "+f"(c[3])
        : "r"(a[0]), "r"(a[1]), "r"(a[2]), "r"(a[3]), "r"(b[0]), "r"(b[1]));
}

// C output: fp16 rows stride H16S, tanh applied. A fp32 stride K.
__global__ void k_gemm_mma_h(const float* __restrict__ A, const float* __restrict__ W,
                             const float* __restrict__ bias, __half* __restrict__ C,
                             int M, int K, int N) {
    constexpr int BM = 128, BN = 128, BK = 32, LDS = BK + 8;
    __shared__ __nv_bfloat16 sAh[BM * LDS], sAl[BM * LDS];
    __shared__ __nv_bfloat16 sBh[BN * LDS], sBl[BN * LDS];

    int tid = threadIdx.x;
    int wid = tid >> 5, lane = tid & 31;
    int wm = wid >> 2, wn = wid & 3;  // 2 x 4 warps; warp tile 64x32
    int bm = blockIdx.y * BM, bn = blockIdx.x * BN;
    const bool kvec = (K % 4) == 0;

    float acc[4][4][4];
#pragma unroll
    for (int i = 0; i < 4; i++)
#pragma unroll
        for (int j = 0; j < 4; j++)
#pragma unroll
            for (int t = 0; t < 4; t++) acc[i][j][t] = 0.0f;

    uint32_t sAh_b = (uint32_t)__cvta_generic_to_shared(sAh);
    uint32_t sAl_b = (uint32_t)__cvta_generic_to_shared(sAl);
    uint32_t sBh_b = (uint32_t)__cvta_generic_to_shared(sBh);
    uint32_t sBl_b = (uint32_t)__cvta_generic_to_shared(sBl);

    for (int k0 = 0; k0 < K; k0 += BK) {
        // ---- A tile: BM x BK fp32 -> bf16 hi/lo ----
#pragma unroll
        for (int i = 0; i < 4; i++) {
            int idx = tid + i * 256;
            int row = idx >> 3;
            int c4  = idx & 7;
            int gm = bm + row;
            int kb = k0 + c4 * 4;
            float v[4] = {0.f, 0.f, 0.f, 0.f};
            if (gm < M) {
                if (kvec && kb + 3 < K) {
                    float4 f = *(const float4*)(A + (size_t)gm * K + kb);
                    v[0] = f.x; v[1] = f.y; v[2] = f.z; v[3] = f.w;
                } else {
#pragma unroll
                    for (int j = 0; j < 4; j++)
                        if (kb + j < K) v[j] = A[(size_t)gm * K + kb + j];
                }
            }
#pragma unroll
            for (int j = 0; j < 4; j++) {
                __nv_bfloat16 h = __float2bfloat16(v[j]);
                __nv_bfloat16 l = __float2bfloat16(v[j] - __bfloat162float(h));
                sAh[row * LDS + c4 * 4 + j] = h;
                sAl[row * LDS + c4 * 4 + j] = l;
            }
        }
        // ---- B tile: W[k0..k0+31][bn..bn+127], float4 along n ----
#pragma unroll
        for (int i = 0; i < 4; i++) {
            int idx = tid + i * 256;      // 0..1023
            int kk = idx >> 5;            // 0..31
            int n4 = (idx & 31) * 4;      // 0..124
            int gk = k0 + kk, gn = bn + n4;
            float v[4] = {0.f, 0.f, 0.f, 0.f};
            if (gk < K) {
                if (gn + 3 < N) {
                    float4 f = *(const float4*)(W + (size_t)gk * N + gn);
                    v[0] = f.x; v[1] = f.y; v[2] = f.z; v[3] = f.w;
                } else {
#pragma unroll
                    for (int j = 0; j < 4; j++)
                        if (gn + j < N) v[j] = W[(size_t)gk * N + gn + j];
                }
            }
#pragma unroll
            for (int j = 0; j < 4; j++) {
                __nv_bfloat16 h = __float2bfloat16(v[j]);
                __nv_bfloat16 l = __float2bfloat16(v[j] - __bfloat162float(h));
                sBh[(n4 + j) * LDS + kk] = h;
                sBl[(n4 + j) * LDS + kk] = l;
            }
        }
        __syncthreads();

        // ---- compute: 2 k-steps of 16 ----
#pragma unroll
        for (int ks = 0; ks < 2; ks++) {
            int koff = ks * 16;
            uint32_t ah[4][4], al[4][4];
#pragma unroll
            for (int mf = 0; mf < 4; mf++) {
                int r = wm * 64 + mf * 16 + (lane & 15);
                uint32_t off = (uint32_t)(r * LDS + koff + ((lane >> 4) << 3)) * 2;
                ldm_x4(sAh_b + off, ah[mf][0], ah[mf][1], ah[mf][2], ah[mf][3]);
                ldm_x4(sAl_b + off, al[mf][0], al[mf][1], al[mf][2], al[mf][3]);
            }
            uint32_t bh[4][2], bl[4][2];
#pragma unroll
            for (int nf2 = 0; nf2 < 2; nf2++) {
                int n = wn * 32 + nf2 * 16 + (lane & 7) + ((lane & 16) >> 1);
                int kl = koff + (((lane >> 3) & 1) << 3);
                uint32_t off = (uint32_t)(n * LDS + kl) * 2;
                uint32_t r0, r1, r2, r3;
                ldm_x4(sBh_b + off, r0, r1, r2, r3);
                bh[nf2 * 2][0] = r0; bh[nf2 * 2][1] = r1;
                bh[nf2 * 2 + 1][0] = r2; bh[nf2 * 2 + 1][1] = r3;
                ldm_x4(sBl_b + off, r0, r1, r2, r3);
                bl[nf2 * 2][0] = r0; bl[nf2 * 2][1] = r1;
                bl[nf2 * 2 + 1][0] = r2; bl[nf2 * 2 + 1][1] = r3;
            }
#pragma unroll
            for (int mf = 0; mf < 4; mf++)
#pragma unroll
                for (int nf = 0; nf < 4; nf++) {
                    mma_bf16(acc[mf][nf], ah[mf], bh[nf]);
                    mma_bf16(acc[mf][nf], ah[mf], bl[nf]);
                    mma_bf16(acc[mf][nf], al[mf], bh[nf]);
                }
        }
        __syncthreads();
    }

    // ---- epilogue: tanh -> fp16 rows (stride H16S) ----
#pragma unroll
    for (int mf = 0; mf < 4; mf++) {
        int r0 = bm + wm * 64 + mf * 16 + (lane >> 2);
        int r1 = r0 + 8;
#pragma unroll
        for (int nf = 0; nf < 4; nf++) {
            int col = bn + wn * 32 + nf * 8 + (lane & 3) * 2;
#pragma unroll
            for (int j = 0; j < 2; j++) {
                int gn = col + j;
                if (gn >= N) continue;
                float bb = bias[gn];
                if (r0 < M)
                    C[(size_t)r0 * H16S + gn] = __float2half(tanhf(acc[mf][nf][j] + bb));
                if (r1 < M)
                    C[(size_t)r1 * H16S + gn] = __float2half(tanhf(acc[mf][nf][2 + j] + bb));
            }
        }
    }
}

// ---------------- fp32 SIMT GEMM, fp16 A input (tiny layer 3) ---------------
__global__ void k_gemm_h16(const __half* __restrict__ A, const float* __restrict__ W,
                           float* __restrict__ C, int M, int K, int N, int lda) {
    constexpr int BM = 128, BN = 64, BK = 16;
    __shared__ float As[BK][BM + 1];
    __shared__ float Bs[BK][BN];

    int bm = blockIdx.y * BM;
    int bn = blockIdx.x * BN;
    int tid = threadIdx.x;
    int tr = tid >> 4;
    int tc = tid & 15;

    float acc[8][4];
#pragma unroll
    for (int i = 0; i < 8; i++)
#pragma unroll
        for (int j = 0; j < 4; j++) acc[i][j] = 0.0f;

    for (int k0 = 0; k0 < K; k0 += BK) {
#pragma unroll
        for (int i = 0; i < 8; i++) {
            int idx = tid + i * 256;
            int m = idx >> 4;
            int kk = idx & 15;
            int gm = bm + m, gk = k0 + kk;
            float v = 0.0f;
            if (gm < M && gk < K)
                v = __half2float(A[(size_t)gm * lda + gk]) * g_inv_out[gm];
            As[kk][m] = v;
        }
#pragma unroll
        for (int i = 0; i < 4; i++) {
            int idx = tid + i * 256;
            int kk = idx >> 6;
            int n = idx & 63;
            int gk = k0 + kk, gn = bn + n;
            Bs[kk][n] = (gk < K && gn < N) ? W[(size_t)gk * N + gn] : 0.0f;
        }
        __syncthreads();
#pragma unroll
        for (int kk = 0; kk < BK; kk++) {
            float a[8], b[4];
#pragma unroll
            for (int i = 0; i < 8; i++) a[i] = As[kk][tr * 8 + i];
#pragma unroll
            for (int j = 0; j < 4; j++) b[j] = Bs[kk][tc * 4 + j];
#pragma unroll
            for (int i = 0; i < 8; i++)
#pragma unroll
                for (int j = 0; j < 4; j++) acc[i][j] += a[i] * b[j];
        }
        __syncthreads();
    }

#pragma unroll
    for (int i = 0; i < 8; i++) {
        int gm = bm + tr * 8 + i;
        if (gm >= M) continue;
#pragma unroll
        for (int j = 0; j < 4; j++) {
            int gn = bn + tc * 4 + j;
            if (gn >= N) continue;
            C[(size_t)gm * N + gn] = acc[i][j];
        }
    }
}

// ---------------- launch -----------------------------------------------------
extern "C" void kernel_launch(void* const* d_in, const int* in_sizes, int n_in,
                              void* d_out, int out_size) {
    const float* x  = nullptr;
    const float* W0 = nullptr; const float* W1 = nullptr;
    const float* W2 = nullptr; const float* W3 = nullptr;
    const float* b0 = nullptr; const float* b1 = nullptr;
    const float* b2 = nullptr; const float* b3 = nullptr;
    const void*  ei = nullptr;

    int n220 = 0, nbias = 0;
    for (int i = 0; i < n_in; i++) {
        int s = in_sizes[i];
        const void* p = d_in[i];
        switch (s) {
            case 1100000: x  = (const float*)p; break;
            case 4840:    W0 = (const float*)p; break;
            case 48400:   if (n220 == 0) W1 = (const float*)p;
                          else           W2 = (const float*)p;
                          n220++; break;
            case 2200:    W3 = (const float*)p; break;
            case 220:     if (nbias == 0) b0 = (const float*)p;
                          else if (nbias == 1) b1 = (const float*)p;
                          else b2 = (const float*)p;
                          nbias++; break;
            case 10:      b3 = (const float*)p; break;
            case 1600000: ei = p; break;
            default: break;
        }
    }
    float* out = (float*)d_out;

    float* bufA = nullptr; __half* h16 = nullptr;
    if (cudaGetSymbolAddress((void**)&bufA, g_bufA) != cudaSuccess) return;
    if (cudaGetSymbolAddress((void**)&h16, g_h16) != cudaSuccess) return;
    if (!x || !W0 || !W1 || !W2 || !W3 || !b0 || !b1 || !b2 || !b3 || !ei) return;

    const int TB = 256;
    // graph prep
    k_detect<<<1, 32>>>((const int*)ei);
    k_convert<<<(NE + TB - 1) / TB, TB>>>(ei);
    k_init_deg<<<(NN + TB - 1) / TB, TB>>>();
    k_degrees<<<(NE + TB - 1) / TB, TB>>>();
    k_invsqrt<<<(NN + TB - 1) / TB, TB>>>();
    k_scan<<<1, 1024>>>();
    k_fill<<<(NE + TB - 1) / TB, TB>>>();

    const int AGG_BLOCKS = (NN + 7) / 8;  // 8 warps/block
    dim3 mma_grid((220 + 127) / 128, (NN + 127) / 128);
    dim3 gemm_grid3(1, (NN + 127) / 128);

    // Layer 0: agg(x fp32, F=22) -> bufA ; mma 22->220 +b0, tanh -> h16
    k_aggregate<22, true, false><<<AGG_BLOCKS, TB>>>(x, bufA, nullptr);
    k_gemm_mma_h<<<mma_grid, TB>>>(bufA, W0, b0, h16, NN, 22, 220);

    // Layer 1: agg fp16 (8-edge batched) -> bufA fp32 ; mma -> h16
    k_aggregate220_f16<<<AGG_BLOCKS, TB>>>(h16, bufA);
    k_gemm_mma_h<<<mma_grid, TB>>>(bufA, W1, b1, h16, NN, 220, 220);

    // Layer 2
    k_aggregate220_f16<<<AGG_BLOCKS, TB>>>(h16, bufA);
    k_gemm_mma_h<<<mma_grid, TB>>>(bufA, W2, b2, h16, NN, 220, 220);

    // Layer 3 (reordered): z = (h*inv_out) @ W3 -> bufA[N,10]; agg 10-wide + b3
    k_gemm_h16<<<gemm_grid3, TB>>>(h16, W3, bufA, NN, 220, 10, H16S);
    k_aggregate<10, false, true><<<AGG_BLOCKS, TB>>>(bufA, out, b3);
}